// round 12
// baseline (speedup 1.0000x reference)
#include <cuda_runtime.h>
#include <cuda_bf16.h>
#include <math.h>
#include <stdint.h>

// Problem constants
#define BB   2
#define NN   4096
#define BNP  (BB*NN)        // 8192 rows
#define DIMV 256
#define KNNV 16
#define M2   (BNP*KNNV)     // 131072 rows

typedef __nv_bfloat16 bf16;
typedef __nv_bfloat162 bf162;

// -------------------- scratch --------------------
__device__ float g_qa [BNP*DIMV];
__device__ float g_ka [BNP*DIMV];
__device__ bf16  g_v  [BNP*DIMV];
__device__ bf16  g_agg[BNP*DIMV];
__device__ int   g_idx[M2];
__device__ bf16  g_h  [(size_t)M2*DIMV];
__device__ bf16  g_pe [(size_t)M2*DIMV];
__device__ bf16  g_h2 [(size_t)M2*DIMV];
__device__ bf16  g_wt [7*DIMV*DIMV];       // transposed bf16 weights [n][k]
__device__ bf16  g_xb [BNP*DIMV];
__device__ float g_bpa[DIMV];

#define WT_WV  0
#define WT_PW2 1
#define WT_AW2 2
#define WT_FW  3
#define WT_WQA 4
#define WT_WKA 5
#define WT_WPA 6

// epilogue flags
#define F_RELU    1
#define F_OBF     2
#define F_QK      4
#define F_SOFTAGG 8

// ==================== bf16 mma.sync GEMM, A fully staged ====================
// CTA tile 128x128. A: M x 256 bf16 row-major, staged ONCE in smem (stride 264,
// LDSM conflict-free). Bt: 256x256 bf16 transposed [n][k], double-buffered in
// 64-k tiles. 8 warps (2x4), mma.m16n8k16, ldmatrix frags.
// Dual mode: grid.x=4, CTAs 0-1 use (Bt0,...), 2-3 use (Bt1,...).

#define ASTR2 264                       // bf16 elems per A smem row
#define A_BYTES (128*ASTR2*2)           // 67584
#define BSTR  72                        // bf16 elems per B smem row
#define BT_ELEMS (128*BSTR)             // one B tile (bf16 elems)
#define GEMM_SMEM_BYTES (A_BYTES + 2*BT_ELEMS*2)   // 104448
#define RSTR 132                        // softagg staging stride (floats)

__device__ __forceinline__ void cp16b(bf16* s, const bf16* g) {
    uint32_t sa = (uint32_t)__cvta_generic_to_shared(s);
    asm volatile("cp.async.cg.shared.global [%0], [%1], 16;\n" :: "r"(sa), "l"(g));
}

#define LDSM4(r0, r1, r2, r3, addr)                                          \
    asm volatile("ldmatrix.sync.aligned.m8n8.x4.shared.b16 {%0,%1,%2,%3}, [%4];" \
                 : "=r"(r0), "=r"(r1), "=r"(r2), "=r"(r3) : "r"(addr))

__global__ __launch_bounds__(256, 2)
void gemm_bf16_kernel(const bf16* __restrict__ A,
                      const bf16* __restrict__ Bt0, const bf16* __restrict__ Bt1,
                      const float* __restrict__ bias0, const float* __restrict__ bias1,
                      const float* __restrict__ qa, const float* __restrict__ ka,
                      const float* __restrict__ resid,
                      void* __restrict__ out0, void* __restrict__ out1,
                      int flags0, int flags1)
{
    extern __shared__ bf16 smem[];
    bf16* As = smem;                       // [128][ASTR2]
    bf16* Bs = smem + 128 * ASTR2;         // [2][128][BSTR]

    const int tid  = threadIdx.x;
    const int lane = tid & 31;
    const int warp = tid >> 5;
    const int wm   = warp >> 2;       // 0..1  -> 64 rows
    const int wn   = warp & 3;        // 0..3  -> 32 cols
    const int bm   = blockIdx.y * 128;

    int sub, bn;
    if (Bt1) { sub = blockIdx.x >> 1; bn = (blockIdx.x & 1) * 128; }
    else     { sub = 0;               bn = blockIdx.x * 128; }
    const bf16*  Bt    = sub ? Bt1    : Bt0;
    const float* bias  = sub ? bias1  : bias0;
    void*        Cout  = sub ? out1   : out0;
    const int    flags = sub ? flags1 : flags0;

    const int g  = lane >> 2;         // groupID 0..7
    const int tg = lane & 3;          // thread-in-group 0..3

    float acc[4][4][4];
#pragma unroll
    for (int i = 0; i < 4; ++i)
#pragma unroll
        for (int j = 0; j < 4; ++j)
#pragma unroll
            for (int c = 0; c < 4; ++c) acc[i][j][c] = 0.f;

    // ---- issue ALL A loads (16/thread: 128 rows x 32 chunks) + B tile 0 ----
#pragma unroll
    for (int i = 0; i < 16; ++i) {
        int idx = tid + i * 256;          // 0..4095
        int row = idx >> 5;               // 0..127
        int c32 = idx & 31;               // 16B chunk in row (32 per row)
        cp16b(&As[row * ASTR2 + c32 * 8],
              A + (size_t)(bm + row) * 256 + c32 * 8);
    }
    auto load_B = [&](int buf, int k0) {
#pragma unroll
        for (int u = 0; u < 4; ++u) {
            int idx = tid + u * 256;
            int row = idx >> 3;               // n index 0..127
            int c8  = idx & 7;
            cp16b(&Bs[buf * BT_ELEMS + row * BSTR + c8 * 8],
                  Bt + (size_t)(bn + row) * 256 + k0 + c8 * 8);
        }
        asm volatile("cp.async.commit_group;\n");
    };
    load_B(0, 0);        // group 0 (contains A too)

    // ldmatrix per-lane base addresses
    const int sel  = lane >> 3;       // 0..3
    const int rsub = lane & 7;
    const uint32_t sA = (uint32_t)__cvta_generic_to_shared(As);
    const uint32_t sB = (uint32_t)__cvta_generic_to_shared(Bs);
    const uint32_t aBase =
        sA + (uint32_t)(((wm * 64 + rsub + (sel & 1) * 8) * ASTR2 + (sel >> 1) * 8) * 2);
    const uint32_t bBase =
        sB + (uint32_t)(((wn * 32 + rsub + (sel & 1) * 8) * BSTR + (sel >> 1) * 8) * 2);

    for (int t = 0; t < 4; ++t) {
        const int buf = t & 1;
        if (t < 3) {
            load_B(buf ^ 1, (t + 1) * 64);
            asm volatile("cp.async.wait_group 1;\n" ::: "memory");
        } else {
            asm volatile("cp.async.wait_group 0;\n" ::: "memory");
        }
        __syncthreads();

        const uint32_t bT = bBase + (uint32_t)buf * (BT_ELEMS * 2);

#pragma unroll
        for (int ks4 = 0; ks4 < 4; ++ks4) {
            const int ks = t * 4 + ks4;                 // 0..15
            const uint32_t aoff = (uint32_t)ks * 32;    // 16 bf16 = 32B
            const uint32_t koff = (uint32_t)ks4 * 32;
            uint32_t af[4][4], bfr[4][2];
#pragma unroll
            for (int mt = 0; mt < 4; ++mt) {
                LDSM4(af[mt][0], af[mt][1], af[mt][2], af[mt][3],
                      aBase + (uint32_t)(mt * 16 * ASTR2 * 2) + aoff);
            }
#pragma unroll
            for (int p = 0; p < 2; ++p) {
                LDSM4(bfr[2 * p][0], bfr[2 * p + 1][0], bfr[2 * p][1], bfr[2 * p + 1][1],
                      bT + (uint32_t)(p * 16 * BSTR * 2) + koff);
            }
#pragma unroll
            for (int mt = 0; mt < 4; ++mt)
#pragma unroll
                for (int nt = 0; nt < 4; ++nt) {
                    asm volatile(
                        "mma.sync.aligned.m16n8k16.row.col.f32.bf16.bf16.f32 "
                        "{%0,%1,%2,%3}, {%4,%5,%6,%7}, {%8,%9}, {%0,%1,%2,%3};\n"
                        : "+f"(acc[mt][nt][0]), "+f"(acc[mt][nt][1]),
                          "+f"(acc[mt][nt][2]), "+f"(acc[mt][nt][3])
                        : "r"(af[mt][0]), "r"(af[mt][1]), "r"(af[mt][2]), "r"(af[mt][3]),
                          "r"(bfr[nt][0]), "r"(bfr[nt][1]));
                }
        }
        __syncthreads();   // protect B buffer reuse (and A region for softagg)
    }

    // ==================== epilogues ====================
    if (flags & F_SOFTAGG) {
        // Stage the 128x128 tile in smem (reuses the A region — 67584 B),
        // then per-(query, channel) serial softmax over K + aggregate.
        float* sred = (float*)smem;                 // [128][RSTR]
        const float inv_scale = 1.0f / 16.0f;       // 1/sqrt(256)
#pragma unroll
        for (int mt = 0; mt < 4; ++mt)
#pragma unroll
            for (int nt = 0; nt < 4; ++nt) {
                int rl = wm * 64 + mt * 16 + g;
                int cl = wn * 32 + nt * 8 + 2 * tg;
                sred[rl * RSTR + cl]           = (acc[mt][nt][0] + bias[bn + cl])     * inv_scale;
                sred[rl * RSTR + cl + 1]       = (acc[mt][nt][1] + bias[bn + cl + 1]) * inv_scale;
                sred[(rl + 8) * RSTR + cl]     = (acc[mt][nt][2] + bias[bn + cl])     * inv_scale;
                sred[(rl + 8) * RSTR + cl + 1] = (acc[mt][nt][3] + bias[bn + cl + 1]) * inv_scale;
            }
        __syncthreads();
#pragma unroll
        for (int i = 0; i < 4; ++i) {
            const int p  = tid + i * 256;     // 0..1023
            const int q  = p >> 7;            // local query 0..7
            const int c  = p & 127;           // local channel
            const int m0 = bm + q * 16;       // global row of neighbor k=0
            float vals[KNNV];
            float mx = -3.4e38f;
#pragma unroll
            for (int k = 0; k < KNNV; ++k) {
                vals[k] = sred[(q * 16 + k) * RSTR + c];
                mx = fmaxf(mx, vals[k]);
            }
            float s = 0.f, accv = 0.f;
#pragma unroll
            for (int k = 0; k < KNNV; ++k) {
                float e = __expf(vals[k] - mx);
                int r = g_idx[m0 + k];
                float pv = __bfloat162float(g_pe[(size_t)(m0 + k) * 256 + bn + c])
                         + __bfloat162float(g_v [(size_t)r * 256 + bn + c]);
                s += e;
                accv = fmaf(e, pv, accv);
            }
            const int qg = m0 >> 4;           // global query row
            ((bf16*)Cout)[(size_t)qg * 256 + bn + c] = __float2bfloat16_rn(accv / s);
        }
        return;
    }

    const bool doRelu = flags & F_RELU;
    const bool obf    = flags & F_OBF;
    const bool doQK   = flags & F_QK;
#pragma unroll
    for (int mt = 0; mt < 4; ++mt) {
#pragma unroll
        for (int nt = 0; nt < 4; ++nt) {
            int row0 = bm + wm * 64 + mt * 16 + g;
            int col0 = bn + wn * 32 + nt * 8 + 2 * tg;
#pragma unroll
            for (int h = 0; h < 2; ++h) {
                int row = row0 + h * 8;
                float c0 = acc[mt][nt][2 * h];
                float c1 = acc[mt][nt][2 * h + 1];
                if (bias) { c0 += bias[col0]; c1 += bias[col0 + 1]; }
                if (doQK) {
                    int n = row >> 4;
                    int r = g_idx[row];
                    float2 qv = *(const float2*)(qa + (size_t)n * 256 + col0);
                    float2 kv = *(const float2*)(ka + (size_t)r * 256 + col0);
                    c0 += qv.x - kv.x;
                    c1 += qv.y - kv.y;
                }
                if (doRelu) { c0 = fmaxf(c0, 0.f); c1 = fmaxf(c1, 0.f); }
                if (obf) {
                    *(bf162*)((bf16*)Cout + (size_t)row * 256 + col0) =
                        __floats2bfloat162_rn(c0, c1);
                } else {
                    if (resid) {
                        c0 += resid[(size_t)row * 256 + col0];
                        c1 += resid[(size_t)row * 256 + col0 + 1];
                    }
                    *(float2*)((float*)Cout + (size_t)row * 256 + col0) =
                        make_float2(c0, c1);
                }
            }
        }
    }
}

// -------------------- prep: convert / transpose / fold --------------------
struct WSrcs { const float* p[4]; };   // wv, pw2, aw2, fw

__global__ __launch_bounds__(256)
void conv_weights_kernel(WSrcs ws)
{
    const int sel = blockIdx.x >> 8;
    const int n   = blockIdx.x & 255;
    const int k   = threadIdx.x;
    g_wt[(size_t)sel * 65536 + n * 256 + k] =
        __float2bfloat16_rn(ws.p[sel][k * 256 + n]);
}

// Wqa = wq@aw1, Wka = wk@aw1, Wpa = pw2@aw1 (stored transposed, bf16),
// bpa = pb2@aw1 + ab1 (fp32)
__global__ __launch_bounds__(256)
void fold_kernel(const float* __restrict__ wq, const float* __restrict__ wk,
                 const float* __restrict__ pw2, const float* __restrict__ aw1,
                 const float* __restrict__ pb2, const float* __restrict__ ab1)
{
    const int b = blockIdx.x;
    const int j = threadIdx.x;
    if (b < 768) {
        const int sel = b >> 8;
        const int i   = b & 255;
        const float* src = (sel == 0) ? wq : (sel == 1) ? wk : pw2;
        float s = 0.f;
        for (int d = 0; d < 256; ++d)
            s = fmaf(src[i * 256 + d], aw1[d * 256 + j], s);
        g_wt[(size_t)(WT_WQA + sel) * 65536 + j * 256 + i] = __float2bfloat16_rn(s);
    } else {
        float s = ab1[j];
        for (int d = 0; d < 256; ++d)
            s = fmaf(pb2[d], aw1[d * 256 + j], s);
        g_bpa[j] = s;
    }
}

__global__ __launch_bounds__(256)
void conv_x_kernel(const float* __restrict__ x)
{
    const int i4 = blockIdx.x * 256 + threadIdx.x;
    if (i4 < BNP * DIMV / 4) {
        float4 v = *(const float4*)(x + (size_t)i4 * 4);
        bf162* o = (bf162*)(g_xb + (size_t)i4 * 4);
        o[0] = __floats2bfloat162_rn(v.x, v.y);
        o[1] = __floats2bfloat162_rn(v.z, v.w);
    }
}

// -------------------- KNN: warp-collective threshold top-16 --------------------
__device__ __forceinline__ bool dless(float d1, int i1, float d2, int i2) {
    return (d1 < d2) || (d1 == d2 && i1 < i2);
}

#define KNN_SMEM_BYTES (4 * NN * 4)

__global__ __launch_bounds__(256)
void knn_kernel(const float* __restrict__ pos)
{
    extern __shared__ float sm[];
    float* px = sm;
    float* py = sm + NN;
    float* pz = sm + 2 * NN;
    float* sj = sm + 3 * NN;

    const int b = blockIdx.x >> 9;
    const float* pb = pos + (size_t)b * NN * 3;
    for (int j = threadIdx.x; j < NN; j += 256) {
        float x = pb[3 * j], y = pb[3 * j + 1], z = pb[3 * j + 2];
        px[j] = x; py[j] = y; pz[j] = z;
        sj[j] = x * x + y * y + z * z;
    }
    __syncthreads();

    const int warp = threadIdx.x >> 5, lane = threadIdx.x & 31;
    const int q  = blockIdx.x * 8 + warp;
    const int ql = q & (NN - 1);
    const float qx = px[ql], qy = py[ql], qz = pz[ql];
    const float qsq = sj[ql];

    const unsigned FULL = 0xffffffffu;
    float ld  = 3.4e38f; int li   = 0x7fffffff;
    float tau = 3.4e38f; int taui = 0x7fffffff;

#define KNN_INSERT(cd, cj)                                             \
    {                                                                  \
        bool keep = dless(ld, li, (cd), (cj));                         \
        unsigned bal = __ballot_sync(FULL, keep) & 0xffffu;            \
        int p = __popc(bal);                                           \
        float pd = __shfl_up_sync(FULL, ld, 1);                        \
        int   pi = __shfl_up_sync(FULL, li, 1);                        \
        if (lane == p) { ld = (cd); li = (cj); }                       \
        else if (lane > p && lane < 16) { ld = pd; li = pi; }          \
        tau  = __shfl_sync(FULL, ld, 15);                              \
        taui = __shfl_sync(FULL, li, 15);                              \
    }

#define KNN_HANDLE(dd, jj)                                             \
    {                                                                  \
        unsigned any = __ballot_sync(FULL, dless(dd, jj, tau, taui));  \
        while (any) {                                                  \
            int src = __ffs(any) - 1; any &= any - 1;                  \
            float cd = __shfl_sync(FULL, dd, src);                     \
            int   cj = __shfl_sync(FULL, jj, src);                     \
            if (dless(cd, cj, tau, taui)) KNN_INSERT(cd, cj);          \
        }                                                              \
    }

    for (int base = 0; base < NN; base += 128) {
        const int j0 = base + lane;
        const int j1 = j0 + 32;
        const int j2 = j0 + 64;
        const int j3 = j0 + 96;
        float d0 = qsq + sj[j0] - 2.f * (qx * px[j0] + qy * py[j0] + qz * pz[j0]);
        float d1 = qsq + sj[j1] - 2.f * (qx * px[j1] + qy * py[j1] + qz * pz[j1]);
        float d2 = qsq + sj[j2] - 2.f * (qx * px[j2] + qy * py[j2] + qz * pz[j2]);
        float d3 = qsq + sj[j3] - 2.f * (qx * px[j3] + qy * py[j3] + qz * pz[j3]);
        KNN_HANDLE(d0, j0)
        KNN_HANDLE(d1, j1)
        KNN_HANDLE(d2, j2)
        KNN_HANDLE(d3, j3)
    }

    if (lane < KNNV) g_idx[q * KNNV + lane] = b * NN + li;
#undef KNN_INSERT
#undef KNN_HANDLE
}

// ---------- h = relu(rel @ pw1 + pb1) ----------
__global__ __launch_bounds__(256)
void build_h_kernel(const float* __restrict__ pos, const float* __restrict__ pw1,
                    const float* __restrict__ pb1)
{
    const int m = blockIdx.x * 2 + (threadIdx.x >> 7);
    const int d = (threadIdx.x & 127) * 2;
    const int n = m >> 4;
    const int r = g_idx[m];
    const float rx = pos[3 * n]     - pos[3 * r];
    const float ry = pos[3 * n + 1] - pos[3 * r + 1];
    const float rz = pos[3 * n + 2] - pos[3 * r + 2];
    float v0 = pb1[d]   + rx * pw1[d]     + ry * pw1[DIMV + d]     + rz * pw1[2 * DIMV + d];
    float v1 = pb1[d+1] + rx * pw1[d + 1] + ry * pw1[DIMV + d + 1] + rz * pw1[2 * DIMV + d + 1];
    *(bf162*)(g_h + (size_t)m * DIMV + d) =
        __floats2bfloat162_rn(fmaxf(v0, 0.f), fmaxf(v1, 0.f));
}

// -------------------- launch --------------------
extern "C" void kernel_launch(void* const* d_in, const int* in_sizes, int n_in,
                              void* d_out, int out_size)
{
    const float* x   = (const float*)d_in[0];
    const float* pos = (const float*)d_in[1];
    const float* wq  = (const float*)d_in[2];
    const float* wk  = (const float*)d_in[3];
    const float* wv  = (const float*)d_in[4];
    const float* pw1 = (const float*)d_in[5];
    const float* pb1 = (const float*)d_in[6];
    const float* pw2 = (const float*)d_in[7];
    const float* pb2 = (const float*)d_in[8];
    const float* aw1 = (const float*)d_in[9];
    const float* ab1 = (const float*)d_in[10];
    const float* aw2 = (const float*)d_in[11];
    const float* ab2 = (const float*)d_in[12];
    const float* fw  = (const float*)d_in[13];
    const float* fb  = (const float*)d_in[14];
    (void)in_sizes; (void)n_in; (void)out_size;

    float *qa, *ka, *bpa;
    bf16 *v, *agg, *h, *pe, *h2, *wt, *xb;
    cudaGetSymbolAddress((void**)&qa,  g_qa);
    cudaGetSymbolAddress((void**)&ka,  g_ka);
    cudaGetSymbolAddress((void**)&v,   g_v);
    cudaGetSymbolAddress((void**)&agg, g_agg);
    cudaGetSymbolAddress((void**)&h,   g_h);
    cudaGetSymbolAddress((void**)&pe,  g_pe);
    cudaGetSymbolAddress((void**)&h2,  g_h2);
    cudaGetSymbolAddress((void**)&wt,  g_wt);
    cudaGetSymbolAddress((void**)&xb,  g_xb);
    cudaGetSymbolAddress((void**)&bpa, g_bpa);

    cudaFuncSetAttribute(gemm_bf16_kernel,
                         cudaFuncAttributeMaxDynamicSharedMemorySize, GEMM_SMEM_BYTES);
    cudaFuncSetAttribute(knn_kernel,
                         cudaFuncAttributeMaxDynamicSharedMemorySize, KNN_SMEM_BYTES);

    const bf16* wvt  = wt + (size_t)WT_WV  * 65536;
    const bf16* pw2t = wt + (size_t)WT_PW2 * 65536;
    const bf16* aw2t = wt + (size_t)WT_AW2 * 65536;
    const bf16* fwt  = wt + (size_t)WT_FW  * 65536;
    const bf16* wqat = wt + (size_t)WT_WQA * 65536;
    const bf16* wkat = wt + (size_t)WT_WKA * 65536;
    const bf16* wpat = wt + (size_t)WT_WPA * 65536;

    dim3 blk(256);

    // prep
    WSrcs ws; ws.p[0] = wv; ws.p[1] = pw2; ws.p[2] = aw2; ws.p[3] = fw;
    conv_weights_kernel<<<1024, blk>>>(ws);
    fold_kernel<<<769, blk>>>(wq, wk, pw2, aw1, pb2, ab1);
    conv_x_kernel<<<BNP * DIMV / 4 / 256, blk>>>(x);

    // qa & ka (dual, fp32 out)
    gemm_bf16_kernel<<<dim3(4, BNP / 128), blk, GEMM_SMEM_BYTES>>>(
        xb, wqat, wkat, nullptr, nullptr, nullptr, nullptr, nullptr,
        qa, ka, 0, 0);

    // v (bf16 out)
    gemm_bf16_kernel<<<dim3(2, BNP / 128), blk, GEMM_SMEM_BYTES>>>(
        xb, wvt, nullptr, nullptr, nullptr, nullptr, nullptr, nullptr,
        v, nullptr, F_OBF, 0);

    // knn
    knn_kernel<<<BNP / 8, blk, KNN_SMEM_BYTES>>>(pos);

    // h = relu(rel@pw1+pb1)
    build_h_kernel<<<M2 / 2, blk>>>(pos, pw1, pb1);

    // pe = h@pw2 + pb2  AND  h2 = relu(h@Wpa + bpa + qa[n] - ka[r])  (dual)
    gemm_bf16_kernel<<<dim3(4, M2 / 128), blk, GEMM_SMEM_BYTES>>>(
        h, pw2t, wpat, pb2, bpa, qa, ka, nullptr,
        pe, h2, F_OBF, F_OBF | F_RELU | F_QK);

    // agg = softmax_K((h2@aw2 + ab2)/16) . (v[idx] + pe)  — fused, smem-staged
    gemm_bf16_kernel<<<dim3(2, M2 / 128), blk, GEMM_SMEM_BYTES>>>(
        h2, aw2t, nullptr, ab2, nullptr, nullptr, nullptr, nullptr,
        agg, nullptr, F_SOFTAGG, 0);

    // out = agg@fw + fb + x
    gemm_bf16_kernel<<<dim3(2, BNP / 128), blk, GEMM_SMEM_BYTES>>>(
        agg, fwt, nullptr, fb, nullptr, nullptr, nullptr, x,
        (float*)d_out, nullptr, 0, 0);
}

// round 14
// speedup vs baseline: 1.1196x; 1.1196x over previous
#include <cuda_runtime.h>
#include <cuda_bf16.h>
#include <math.h>
#include <stdint.h>

// Problem constants
#define BB   2
#define NN   4096
#define BNP  (BB*NN)        // 8192 rows
#define DIMV 256
#define KNNV 16
#define M2   (BNP*KNNV)     // 131072 rows

typedef __nv_bfloat16 bf16;
typedef __nv_bfloat162 bf162;

// -------------------- scratch --------------------
__device__ float g_qa [BNP*DIMV];
__device__ float g_ka [BNP*DIMV];
__device__ bf16  g_v  [BNP*DIMV];
__device__ bf16  g_agg[BNP*DIMV];
__device__ int   g_idx[M2];
__device__ bf16  g_h  [(size_t)M2*DIMV];
__device__ bf16  g_pe [(size_t)M2*DIMV];
__device__ bf16  g_h2 [(size_t)M2*DIMV];
__device__ bf16  g_wt [7*DIMV*DIMV];       // transposed bf16 weights [n][k]
__device__ bf16  g_xb [BNP*DIMV];
__device__ float g_bpa[DIMV];

#define WT_WV  0
#define WT_PW2 1
#define WT_AW2 2
#define WT_FW  3
#define WT_WQA 4
#define WT_WKA 5
#define WT_WPA 6

// epilogue flags
#define F_RELU    1
#define F_OBF     2
#define F_QK      4
#define F_SOFTAGG 8

// ==================== bf16 mma.sync GEMM, 512 threads ====================
// CTA tile 128x128, BK=64 double-buffered (A and B). 16 warps in a 4x4 grid,
// each warp owns a 32x32 output tile (2x4 mma tiles, 32 acc regs/thread).
// A: M x 256 bf16 row-major. Bt: 256x256 bf16 TRANSPOSED [n][k].
// Dual mode: grid.x=4, CTAs 0-1 use (Bt0,...), 2-3 use (Bt1,...).

#define BKV   64
#define ASTR  72                    // bf16 elems per smem row (144B)
#define TBUF  (128*ASTR)            // one tile buffer (bf16 elems)
#define GEMM_SMEM_BYTES (4*TBUF*2)  // A x2 + B x2 = 73728 B
#define RSTR  132                   // softagg staging stride (floats)

__device__ __forceinline__ void cp16b(bf16* s, const bf16* g) {
    uint32_t sa = (uint32_t)__cvta_generic_to_shared(s);
    asm volatile("cp.async.cg.shared.global [%0], [%1], 16;\n" :: "r"(sa), "l"(g));
}

#define LDSM4(r0, r1, r2, r3, addr)                                          \
    asm volatile("ldmatrix.sync.aligned.m8n8.x4.shared.b16 {%0,%1,%2,%3}, [%4];" \
                 : "=r"(r0), "=r"(r1), "=r"(r2), "=r"(r3) : "r"(addr))

__global__ __launch_bounds__(512, 2)
void gemm_bf16_kernel(const bf16* __restrict__ A,
                      const bf16* __restrict__ Bt0, const bf16* __restrict__ Bt1,
                      const float* __restrict__ bias0, const float* __restrict__ bias1,
                      const float* __restrict__ qa, const float* __restrict__ ka,
                      const float* __restrict__ resid,
                      void* __restrict__ out0, void* __restrict__ out1,
                      int flags0, int flags1)
{
    extern __shared__ bf16 smem[];
    bf16* As = smem;              // [2][128][ASTR]
    bf16* Bs = smem + 2 * TBUF;   // [2][128][ASTR]

    const int tid  = threadIdx.x;
    const int lane = tid & 31;
    const int warp = tid >> 5;        // 0..15
    const int wm   = warp >> 2;       // 0..3  -> 32 rows
    const int wn   = warp & 3;        // 0..3  -> 32 cols
    const int bm   = blockIdx.y * 128;

    int sub, bn;
    if (Bt1) { sub = blockIdx.x >> 1; bn = (blockIdx.x & 1) * 128; }
    else     { sub = 0;               bn = blockIdx.x * 128; }
    const bf16*  Bt    = sub ? Bt1    : Bt0;
    const float* bias  = sub ? bias1  : bias0;
    void*        Cout  = sub ? out1   : out0;
    const int    flags = sub ? flags1 : flags0;

    const int g  = lane >> 2;         // groupID 0..7
    const int tg = lane & 3;          // thread-in-group 0..3

    float acc[2][4][4];
#pragma unroll
    for (int i = 0; i < 2; ++i)
#pragma unroll
        for (int j = 0; j < 4; ++j)
#pragma unroll
            for (int c = 0; c < 4; ++c) acc[i][j][c] = 0.f;

    auto load_tile = [&](int buf, int k0) {
#pragma unroll
        for (int u = 0; u < 2; ++u) {
            int idx = tid + u * 512;          // 0..1023
            int row = idx >> 3;               // 0..127
            int c8  = idx & 7;                // 16B chunk
            cp16b(&As[buf * TBUF + row * ASTR + c8 * 8],
                  A + (size_t)(bm + row) * 256 + k0 + c8 * 8);
        }
#pragma unroll
        for (int u = 0; u < 2; ++u) {
            int idx = tid + u * 512;
            int row = idx >> 3;               // n index 0..127
            int c8  = idx & 7;
            cp16b(&Bs[buf * TBUF + row * ASTR + c8 * 8],
                  Bt + (size_t)(bn + row) * 256 + k0 + c8 * 8);
        }
        asm volatile("cp.async.commit_group;\n");
    };

    load_tile(0, 0);

    // ldmatrix per-lane base addresses
    const int sel  = lane >> 3;       // 0..3
    const int rsub = lane & 7;
    const uint32_t sA = (uint32_t)__cvta_generic_to_shared(As);
    const uint32_t sB = (uint32_t)__cvta_generic_to_shared(Bs);
    const uint32_t aBase =
        sA + (uint32_t)(((wm * 32 + rsub + (sel & 1) * 8) * ASTR + (sel >> 1) * 8) * 2);
    const uint32_t bBase =
        sB + (uint32_t)(((wn * 32 + rsub + (sel & 1) * 8) * ASTR + (sel >> 1) * 8) * 2);

    for (int t = 0; t < 4; ++t) {
        const int buf = t & 1;
        if (t < 3) {
            load_tile(buf ^ 1, (t + 1) * BKV);
            asm volatile("cp.async.wait_group 1;\n" ::: "memory");
        } else {
            asm volatile("cp.async.wait_group 0;\n" ::: "memory");
        }
        __syncthreads();

        const uint32_t aT = aBase + (uint32_t)buf * (TBUF * 2);
        const uint32_t bT = bBase + (uint32_t)buf * (TBUF * 2);

#pragma unroll
        for (int ks = 0; ks < 4; ++ks) {
            const uint32_t koff = ks * 16 * 2;
            uint32_t af[2][4], bfr[4][2];
#pragma unroll
            for (int mt = 0; mt < 2; ++mt) {
                LDSM4(af[mt][0], af[mt][1], af[mt][2], af[mt][3],
                      aT + (uint32_t)(mt * 16 * ASTR * 2) + koff);
            }
#pragma unroll
            for (int p = 0; p < 2; ++p) {
                LDSM4(bfr[2 * p][0], bfr[2 * p + 1][0], bfr[2 * p][1], bfr[2 * p + 1][1],
                      bT + (uint32_t)(p * 16 * ASTR * 2) + koff);
            }
#pragma unroll
            for (int mt = 0; mt < 2; ++mt)
#pragma unroll
                for (int nt = 0; nt < 4; ++nt) {
                    asm volatile(
                        "mma.sync.aligned.m16n8k16.row.col.f32.bf16.bf16.f32 "
                        "{%0,%1,%2,%3}, {%4,%5,%6,%7}, {%8,%9}, {%0,%1,%2,%3};\n"
                        : "+f"(acc[mt][nt][0]), "+f"(acc[mt][nt][1]),
                          "+f"(acc[mt][nt][2]), "+f"(acc[mt][nt][3])
                        : "r"(af[mt][0]), "r"(af[mt][1]), "r"(af[mt][2]), "r"(af[mt][3]),
                          "r"(bfr[nt][0]), "r"(bfr[nt][1]));
                }
        }
        __syncthreads();   // protect buffer reuse (and smem region for softagg)
    }

    // ==================== epilogues ====================
    if (flags & F_SOFTAGG) {
        // Stage the 128x128 tile in smem, then per-(query, channel) serial
        // softmax over K + aggregate with coalesced pe/v gathers.
        float* sred = (float*)smem;                 // [128][RSTR] = 67584 B
        const float inv_scale = 1.0f / 16.0f;       // 1/sqrt(256)
#pragma unroll
        for (int mt = 0; mt < 2; ++mt)
#pragma unroll
            for (int nt = 0; nt < 4; ++nt) {
                int rl = wm * 32 + mt * 16 + g;
                int cl = wn * 32 + nt * 8 + 2 * tg;
                sred[rl * RSTR + cl]           = (acc[mt][nt][0] + bias[bn + cl])     * inv_scale;
                sred[rl * RSTR + cl + 1]       = (acc[mt][nt][1] + bias[bn + cl + 1]) * inv_scale;
                sred[(rl + 8) * RSTR + cl]     = (acc[mt][nt][2] + bias[bn + cl])     * inv_scale;
                sred[(rl + 8) * RSTR + cl + 1] = (acc[mt][nt][3] + bias[bn + cl + 1]) * inv_scale;
            }
        __syncthreads();
#pragma unroll
        for (int i = 0; i < 2; ++i) {
            const int p  = tid + i * 512;     // 0..1023
            const int q  = p >> 7;            // local query 0..7
            const int c  = p & 127;           // local channel
            const int m0 = bm + q * 16;       // global row of neighbor k=0
            float vals[KNNV];
            float mx = -3.4e38f;
#pragma unroll
            for (int k = 0; k < KNNV; ++k) {
                vals[k] = sred[(q * 16 + k) * RSTR + c];
                mx = fmaxf(mx, vals[k]);
            }
            float s = 0.f, accv = 0.f;
#pragma unroll
            for (int k = 0; k < KNNV; ++k) {
                float e = __expf(vals[k] - mx);
                int r = g_idx[m0 + k];
                float pv = __bfloat162float(g_pe[(size_t)(m0 + k) * 256 + bn + c])
                         + __bfloat162float(g_v [(size_t)r * 256 + bn + c]);
                s += e;
                accv = fmaf(e, pv, accv);
            }
            const int qg = m0 >> 4;           // global query row
            ((bf16*)Cout)[(size_t)qg * 256 + bn + c] = __float2bfloat16_rn(accv / s);
        }
        return;
    }

    const bool doRelu = flags & F_RELU;
    const bool obf    = flags & F_OBF;
    const bool doQK   = flags & F_QK;
#pragma unroll
    for (int mt = 0; mt < 2; ++mt) {
#pragma unroll
        for (int nt = 0; nt < 4; ++nt) {
            int row0 = bm + wm * 32 + mt * 16 + g;
            int col0 = bn + wn * 32 + nt * 8 + 2 * tg;
#pragma unroll
            for (int h = 0; h < 2; ++h) {
                int row = row0 + h * 8;
                float c0 = acc[mt][nt][2 * h];
                float c1 = acc[mt][nt][2 * h + 1];
                if (bias) { c0 += bias[col0]; c1 += bias[col0 + 1]; }
                if (doQK) {
                    int n = row >> 4;
                    int r = g_idx[row];
                    float2 qv = *(const float2*)(qa + (size_t)n * 256 + col0);
                    float2 kv = *(const float2*)(ka + (size_t)r * 256 + col0);
                    c0 += qv.x - kv.x;
                    c1 += qv.y - kv.y;
                }
                if (doRelu) { c0 = fmaxf(c0, 0.f); c1 = fmaxf(c1, 0.f); }
                if (obf) {
                    *(bf162*)((bf16*)Cout + (size_t)row * 256 + col0) =
                        __floats2bfloat162_rn(c0, c1);
                } else {
                    if (resid) {
                        c0 += resid[(size_t)row * 256 + col0];
                        c1 += resid[(size_t)row * 256 + col0 + 1];
                    }
                    *(float2*)((float*)Cout + (size_t)row * 256 + col0) =
                        make_float2(c0, c1);
                }
            }
        }
    }
}

// -------------------- prep: convert / transpose / fold --------------------
struct WSrcs { const float* p[4]; };   // wv, pw2, aw2, fw

__global__ __launch_bounds__(256)
void conv_weights_kernel(WSrcs ws)
{
    const int sel = blockIdx.x >> 8;
    const int n   = blockIdx.x & 255;
    const int k   = threadIdx.x;
    g_wt[(size_t)sel * 65536 + n * 256 + k] =
        __float2bfloat16_rn(ws.p[sel][k * 256 + n]);
}

// Wqa = wq@aw1, Wka = wk@aw1, Wpa = pw2@aw1 (stored transposed, bf16),
// bpa = pb2@aw1 + ab1 (fp32)
__global__ __launch_bounds__(256)
void fold_kernel(const float* __restrict__ wq, const float* __restrict__ wk,
                 const float* __restrict__ pw2, const float* __restrict__ aw1,
                 const float* __restrict__ pb2, const float* __restrict__ ab1)
{
    const int b = blockIdx.x;
    const int j = threadIdx.x;
    if (b < 768) {
        const int sel = b >> 8;
        const int i   = b & 255;
        const float* src = (sel == 0) ? wq : (sel == 1) ? wk : pw2;
        float s = 0.f;
        for (int d = 0; d < 256; ++d)
            s = fmaf(src[i * 256 + d], aw1[d * 256 + j], s);
        g_wt[(size_t)(WT_WQA + sel) * 65536 + j * 256 + i] = __float2bfloat16_rn(s);
    } else {
        float s = ab1[j];
        for (int d = 0; d < 256; ++d)
            s = fmaf(pb2[d], aw1[d * 256 + j], s);
        g_bpa[j] = s;
    }
}

__global__ __launch_bounds__(256)
void conv_x_kernel(const float* __restrict__ x)
{
    const int i4 = blockIdx.x * 256 + threadIdx.x;
    if (i4 < BNP * DIMV / 4) {
        float4 v = *(const float4*)(x + (size_t)i4 * 4);
        bf162* o = (bf162*)(g_xb + (size_t)i4 * 4);
        o[0] = __floats2bfloat162_rn(v.x, v.y);
        o[1] = __floats2bfloat162_rn(v.z, v.w);
    }
}

// -------------------- KNN: warp-collective threshold top-16 --------------------
__device__ __forceinline__ bool dless(float d1, int i1, float d2, int i2) {
    return (d1 < d2) || (d1 == d2 && i1 < i2);
}

#define KNN_SMEM_BYTES (4 * NN * 4)

__global__ __launch_bounds__(256)
void knn_kernel(const float* __restrict__ pos)
{
    extern __shared__ float sm[];
    float* px = sm;
    float* py = sm + NN;
    float* pz = sm + 2 * NN;
    float* sj = sm + 3 * NN;

    const int b = blockIdx.x >> 9;
    const float* pb = pos + (size_t)b * NN * 3;
    for (int j = threadIdx.x; j < NN; j += 256) {
        float x = pb[3 * j], y = pb[3 * j + 1], z = pb[3 * j + 2];
        px[j] = x; py[j] = y; pz[j] = z;
        sj[j] = x * x + y * y + z * z;
    }
    __syncthreads();

    const int warp = threadIdx.x >> 5, lane = threadIdx.x & 31;
    const int q  = blockIdx.x * 8 + warp;
    const int ql = q & (NN - 1);
    const float qx = px[ql], qy = py[ql], qz = pz[ql];
    const float qsq = sj[ql];

    const unsigned FULL = 0xffffffffu;
    float ld  = 3.4e38f; int li   = 0x7fffffff;
    float tau = 3.4e38f; int taui = 0x7fffffff;

#define KNN_INSERT(cd, cj)                                             \
    {                                                                  \
        bool keep = dless(ld, li, (cd), (cj));                         \
        unsigned bal = __ballot_sync(FULL, keep) & 0xffffu;            \
        int p = __popc(bal);                                           \
        float pd = __shfl_up_sync(FULL, ld, 1);                        \
        int   pi = __shfl_up_sync(FULL, li, 1);                        \
        if (lane == p) { ld = (cd); li = (cj); }                       \
        else if (lane > p && lane < 16) { ld = pd; li = pi; }          \
        tau  = __shfl_sync(FULL, ld, 15);                              \
        taui = __shfl_sync(FULL, li, 15);                              \
    }

#define KNN_HANDLE(dd, jj)                                             \
    {                                                                  \
        unsigned any = __ballot_sync(FULL, dless(dd, jj, tau, taui));  \
        while (any) {                                                  \
            int src = __ffs(any) - 1; any &= any - 1;                  \
            float cd = __shfl_sync(FULL, dd, src);                     \
            int   cj = __shfl_sync(FULL, jj, src);                     \
            if (dless(cd, cj, tau, taui)) KNN_INSERT(cd, cj);          \
        }                                                              \
    }

    for (int base = 0; base < NN; base += 128) {
        const int j0 = base + lane;
        const int j1 = j0 + 32;
        const int j2 = j0 + 64;
        const int j3 = j0 + 96;
        float d0 = qsq + sj[j0] - 2.f * (qx * px[j0] + qy * py[j0] + qz * pz[j0]);
        float d1 = qsq + sj[j1] - 2.f * (qx * px[j1] + qy * py[j1] + qz * pz[j1]);
        float d2 = qsq + sj[j2] - 2.f * (qx * px[j2] + qy * py[j2] + qz * pz[j2]);
        float d3 = qsq + sj[j3] - 2.f * (qx * px[j3] + qy * py[j3] + qz * pz[j3]);
        KNN_HANDLE(d0, j0)
        KNN_HANDLE(d1, j1)
        KNN_HANDLE(d2, j2)
        KNN_HANDLE(d3, j3)
    }

    if (lane < KNNV) g_idx[q * KNNV + lane] = b * NN + li;
#undef KNN_INSERT
#undef KNN_HANDLE
}

// ---------- h = relu(rel @ pw1 + pb1) ----------
__global__ __launch_bounds__(256)
void build_h_kernel(const float* __restrict__ pos, const float* __restrict__ pw1,
                    const float* __restrict__ pb1)
{
    const int m = blockIdx.x * 2 + (threadIdx.x >> 7);
    const int d = (threadIdx.x & 127) * 2;
    const int n = m >> 4;
    const int r = g_idx[m];
    const float rx = pos[3 * n]     - pos[3 * r];
    const float ry = pos[3 * n + 1] - pos[3 * r + 1];
    const float rz = pos[3 * n + 2] - pos[3 * r + 2];
    float v0 = pb1[d]   + rx * pw1[d]     + ry * pw1[DIMV + d]     + rz * pw1[2 * DIMV + d];
    float v1 = pb1[d+1] + rx * pw1[d + 1] + ry * pw1[DIMV + d + 1] + rz * pw1[2 * DIMV + d + 1];
    *(bf162*)(g_h + (size_t)m * DIMV + d) =
        __floats2bfloat162_rn(fmaxf(v0, 0.f), fmaxf(v1, 0.f));
}

// -------------------- launch --------------------
extern "C" void kernel_launch(void* const* d_in, const int* in_sizes, int n_in,
                              void* d_out, int out_size)
{
    const float* x   = (const float*)d_in[0];
    const float* pos = (const float*)d_in[1];
    const float* wq  = (const float*)d_in[2];
    const float* wk  = (const float*)d_in[3];
    const float* wv  = (const float*)d_in[4];
    const float* pw1 = (const float*)d_in[5];
    const float* pb1 = (const float*)d_in[6];
    const float* pw2 = (const float*)d_in[7];
    const float* pb2 = (const float*)d_in[8];
    const float* aw1 = (const float*)d_in[9];
    const float* ab1 = (const float*)d_in[10];
    const float* aw2 = (const float*)d_in[11];
    const float* ab2 = (const float*)d_in[12];
    const float* fw  = (const float*)d_in[13];
    const float* fb  = (const float*)d_in[14];
    (void)in_sizes; (void)n_in; (void)out_size;

    float *qa, *ka, *bpa;
    bf16 *v, *agg, *h, *pe, *h2, *wt, *xb;
    cudaGetSymbolAddress((void**)&qa,  g_qa);
    cudaGetSymbolAddress((void**)&ka,  g_ka);
    cudaGetSymbolAddress((void**)&v,   g_v);
    cudaGetSymbolAddress((void**)&agg, g_agg);
    cudaGetSymbolAddress((void**)&h,   g_h);
    cudaGetSymbolAddress((void**)&pe,  g_pe);
    cudaGetSymbolAddress((void**)&h2,  g_h2);
    cudaGetSymbolAddress((void**)&wt,  g_wt);
    cudaGetSymbolAddress((void**)&xb,  g_xb);
    cudaGetSymbolAddress((void**)&bpa, g_bpa);

    cudaFuncSetAttribute(gemm_bf16_kernel,
                         cudaFuncAttributeMaxDynamicSharedMemorySize, GEMM_SMEM_BYTES);
    cudaFuncSetAttribute(knn_kernel,
                         cudaFuncAttributeMaxDynamicSharedMemorySize, KNN_SMEM_BYTES);

    const bf16* wvt  = wt + (size_t)WT_WV  * 65536;
    const bf16* pw2t = wt + (size_t)WT_PW2 * 65536;
    const bf16* aw2t = wt + (size_t)WT_AW2 * 65536;
    const bf16* fwt  = wt + (size_t)WT_FW  * 65536;
    const bf16* wqat = wt + (size_t)WT_WQA * 65536;
    const bf16* wkat = wt + (size_t)WT_WKA * 65536;
    const bf16* wpat = wt + (size_t)WT_WPA * 65536;

    dim3 blk(256);
    dim3 gblk(512);

    // prep
    WSrcs ws; ws.p[0] = wv; ws.p[1] = pw2; ws.p[2] = aw2; ws.p[3] = fw;
    conv_weights_kernel<<<1024, blk>>>(ws);
    fold_kernel<<<769, blk>>>(wq, wk, pw2, aw1, pb2, ab1);
    conv_x_kernel<<<BNP * DIMV / 4 / 256, blk>>>(x);

    // qa & ka (dual, fp32 out)
    gemm_bf16_kernel<<<dim3(4, BNP / 128), gblk, GEMM_SMEM_BYTES>>>(
        xb, wqat, wkat, nullptr, nullptr, nullptr, nullptr, nullptr,
        qa, ka, 0, 0);

    // v (bf16 out)
    gemm_bf16_kernel<<<dim3(2, BNP / 128), gblk, GEMM_SMEM_BYTES>>>(
        xb, wvt, nullptr, nullptr, nullptr, nullptr, nullptr, nullptr,
        v, nullptr, F_OBF, 0);

    // knn
    knn_kernel<<<BNP / 8, blk, KNN_SMEM_BYTES>>>(pos);

    // h = relu(rel@pw1+pb1)
    build_h_kernel<<<M2 / 2, blk>>>(pos, pw1, pb1);

    // pe = h@pw2 + pb2  AND  h2 = relu(h@Wpa + bpa + qa[n] - ka[r])  (dual)
    gemm_bf16_kernel<<<dim3(4, M2 / 128), gblk, GEMM_SMEM_BYTES>>>(
        h, pw2t, wpat, pb2, bpa, qa, ka, nullptr,
        pe, h2, F_OBF, F_OBF | F_RELU | F_QK);

    // agg = softmax_K((h2@aw2 + ab2)/16) . (v[idx] + pe)  — fused, smem-staged
    gemm_bf16_kernel<<<dim3(2, M2 / 128), gblk, GEMM_SMEM_BYTES>>>(
        h2, aw2t, nullptr, ab2, nullptr, nullptr, nullptr, nullptr,
        agg, nullptr, F_SOFTAGG, 0);

    // out = agg@fw + fb + x
    gemm_bf16_kernel<<<dim3(2, BNP / 128), gblk, GEMM_SMEM_BYTES>>>(
        agg, fwt, nullptr, fb, nullptr, nullptr, nullptr, x,
        (float*)d_out, nullptr, 0, 0);
}

// round 15
// speedup vs baseline: 1.1370x; 1.0155x over previous
#include <cuda_runtime.h>
#include <cuda_fp16.h>
#include <math.h>
#include <stdint.h>

// Problem constants
#define BB   2
#define NN   4096
#define BNP  (BB*NN)        // 8192 rows
#define DIMV 256
#define KNNV 16
#define M2   (BNP*KNNV)     // 131072 rows

typedef __half h16;

// -------------------- scratch --------------------
__device__ float g_qa [BNP*DIMV];
__device__ float g_ka [BNP*DIMV];
__device__ h16   g_v  [BNP*DIMV];
__device__ h16   g_agg[BNP*DIMV];
__device__ int   g_idx[M2];
__device__ h16   g_h  [(size_t)M2*DIMV];
__device__ h16   g_pe [(size_t)M2*DIMV];
__device__ h16   g_h2 [(size_t)M2*DIMV];
__device__ h16   g_wt [7*DIMV*DIMV];       // transposed fp16 weights [n][k]
__device__ h16   g_xb [BNP*DIMV];
__device__ float g_bpa[DIMV];

#define WT_WV  0
#define WT_PW2 1
#define WT_AW2 2
#define WT_FW  3
#define WT_WQA 4
#define WT_WKA 5
#define WT_WPA 6

// epilogue flags
#define F_RELU    1
#define F_OH16    2
#define F_QK      4
#define F_SOFTAGG 8

// ==================== fp16 mma.sync GEMM (f16 accumulate), 512 threads ====
// CTA tile 128x128, BK=64 double-buffered. 16 warps (4x4), 32x32 per warp.
// A: M x 256 fp16 row-major. Bt: 256x256 fp16 TRANSPOSED [n][k].
// Multi mode: grid.x = 2*nsub; CTA pair i uses (Bt_i, bias_i, out_i, flags_i).

#define BKV   64
#define ASTR  72                    // fp16 elems per smem row (144B)
#define TBUF  (128*ASTR)            // one tile buffer (fp16 elems)
#define GEMM_SMEM_BYTES (4*TBUF*2)  // A x2 + B x2 = 73728 B
#define RSTR  132                   // softagg staging stride (floats)

__device__ __forceinline__ void cp16h(h16* s, const h16* g) {
    uint32_t sa = (uint32_t)__cvta_generic_to_shared(s);
    asm volatile("cp.async.cg.shared.global [%0], [%1], 16;\n" :: "r"(sa), "l"(g));
}

#define LDSM4(r0, r1, r2, r3, addr)                                          \
    asm volatile("ldmatrix.sync.aligned.m8n8.x4.shared.b16 {%0,%1,%2,%3}, [%4];" \
                 : "=r"(r0), "=r"(r1), "=r"(r2), "=r"(r3) : "r"(addr))

#define MMA_F16(c0, c1, a0, a1, a2, a3, b0, b1)                              \
    asm volatile("mma.sync.aligned.m16n8k16.row.col.f16.f16.f16.f16 "        \
                 "{%0,%1}, {%2,%3,%4,%5}, {%6,%7}, {%0,%1};\n"               \
                 : "+r"(c0), "+r"(c1)                                        \
                 : "r"(a0), "r"(a1), "r"(a2), "r"(a3), "r"(b0), "r"(b1))

__global__ __launch_bounds__(512, 2)
void gemm_f16_kernel(const h16* __restrict__ A,
                     const h16* __restrict__ Bt0, const h16* __restrict__ Bt1,
                     const h16* __restrict__ Bt2,
                     const float* __restrict__ bias0, const float* __restrict__ bias1,
                     const float* __restrict__ bias2,
                     const float* __restrict__ qa, const float* __restrict__ ka,
                     const float* __restrict__ resid,
                     void* __restrict__ out0, void* __restrict__ out1,
                     void* __restrict__ out2,
                     int flags0, int flags1, int flags2)
{
    extern __shared__ h16 smem[];
    h16* As = smem;              // [2][128][ASTR]
    h16* Bs = smem + 2 * TBUF;   // [2][128][ASTR]

    const int tid  = threadIdx.x;
    const int lane = tid & 31;
    const int warp = tid >> 5;        // 0..15
    const int wm   = warp >> 2;       // 0..3  -> 32 rows
    const int wn   = warp & 3;        // 0..3  -> 32 cols
    const int bm   = blockIdx.y * 128;

    int sub, bn;
    if (Bt1) { sub = blockIdx.x >> 1; bn = (blockIdx.x & 1) * 128; }
    else     { sub = 0;               bn = blockIdx.x * 128; }
    const h16*   Bt    = (sub == 2) ? Bt2    : (sub == 1) ? Bt1    : Bt0;
    const float* bias  = (sub == 2) ? bias2  : (sub == 1) ? bias1  : bias0;
    void*        Cout  = (sub == 2) ? out2   : (sub == 1) ? out1   : out0;
    const int    flags = (sub == 2) ? flags2 : (sub == 1) ? flags1 : flags0;

    const int g  = lane >> 2;         // groupID 0..7
    const int tg = lane & 3;          // thread-in-group 0..3

    // f16 accumulators: [mt][nt][2] regs, each reg = 2 halves
    uint32_t acc[2][4][2];
#pragma unroll
    for (int i = 0; i < 2; ++i)
#pragma unroll
        for (int j = 0; j < 4; ++j) { acc[i][j][0] = 0u; acc[i][j][1] = 0u; }

    auto load_tile = [&](int buf, int k0) {
#pragma unroll
        for (int u = 0; u < 2; ++u) {
            int idx = tid + u * 512;          // 0..1023
            int row = idx >> 3;               // 0..127
            int c8  = idx & 7;                // 16B chunk
            cp16h(&As[buf * TBUF + row * ASTR + c8 * 8],
                  A + (size_t)(bm + row) * 256 + k0 + c8 * 8);
        }
#pragma unroll
        for (int u = 0; u < 2; ++u) {
            int idx = tid + u * 512;
            int row = idx >> 3;               // n index 0..127
            int c8  = idx & 7;
            cp16h(&Bs[buf * TBUF + row * ASTR + c8 * 8],
                  Bt + (size_t)(bn + row) * 256 + k0 + c8 * 8);
        }
        asm volatile("cp.async.commit_group;\n");
    };

    load_tile(0, 0);

    // ldmatrix per-lane base addresses
    const int sel  = lane >> 3;       // 0..3
    const int rsub = lane & 7;
    const uint32_t sA = (uint32_t)__cvta_generic_to_shared(As);
    const uint32_t sB = (uint32_t)__cvta_generic_to_shared(Bs);
    const uint32_t aBase =
        sA + (uint32_t)(((wm * 32 + rsub + (sel & 1) * 8) * ASTR + (sel >> 1) * 8) * 2);
    const uint32_t bBase =
        sB + (uint32_t)(((wn * 32 + rsub + (sel & 1) * 8) * ASTR + (sel >> 1) * 8) * 2);

    for (int t = 0; t < 4; ++t) {
        const int buf = t & 1;
        if (t < 3) {
            load_tile(buf ^ 1, (t + 1) * BKV);
            asm volatile("cp.async.wait_group 1;\n" ::: "memory");
        } else {
            asm volatile("cp.async.wait_group 0;\n" ::: "memory");
        }
        __syncthreads();

        const uint32_t aT = aBase + (uint32_t)buf * (TBUF * 2);
        const uint32_t bT = bBase + (uint32_t)buf * (TBUF * 2);

#pragma unroll
        for (int ks = 0; ks < 4; ++ks) {
            const uint32_t koff = ks * 16 * 2;
            uint32_t af[2][4], bfr[4][2];
#pragma unroll
            for (int mt = 0; mt < 2; ++mt) {
                LDSM4(af[mt][0], af[mt][1], af[mt][2], af[mt][3],
                      aT + (uint32_t)(mt * 16 * ASTR * 2) + koff);
            }
#pragma unroll
            for (int p = 0; p < 2; ++p) {
                LDSM4(bfr[2 * p][0], bfr[2 * p + 1][0], bfr[2 * p][1], bfr[2 * p + 1][1],
                      bT + (uint32_t)(p * 16 * ASTR * 2) + koff);
            }
#pragma unroll
            for (int mt = 0; mt < 2; ++mt)
#pragma unroll
                for (int nt = 0; nt < 4; ++nt) {
                    MMA_F16(acc[mt][nt][0], acc[mt][nt][1],
                            af[mt][0], af[mt][1], af[mt][2], af[mt][3],
                            bfr[nt][0], bfr[nt][1]);
                }
        }
        __syncthreads();   // protect buffer reuse (and smem region for softagg)
    }

    // ==================== epilogues ====================
    if (flags & F_SOFTAGG) {
        float* sred = (float*)smem;                 // [128][RSTR] = 67584 B
        const float inv_scale = 1.0f / 16.0f;       // 1/sqrt(256)
#pragma unroll
        for (int mt = 0; mt < 2; ++mt)
#pragma unroll
            for (int nt = 0; nt < 4; ++nt) {
                int rl = wm * 32 + mt * 16 + g;
                int cl = wn * 32 + nt * 8 + 2 * tg;
                float2 lo = __half22float2(*(const __half2*)&acc[mt][nt][0]);
                float2 hi = __half22float2(*(const __half2*)&acc[mt][nt][1]);
                sred[rl * RSTR + cl]           = (lo.x + bias[bn + cl])     * inv_scale;
                sred[rl * RSTR + cl + 1]       = (lo.y + bias[bn + cl + 1]) * inv_scale;
                sred[(rl + 8) * RSTR + cl]     = (hi.x + bias[bn + cl])     * inv_scale;
                sred[(rl + 8) * RSTR + cl + 1] = (hi.y + bias[bn + cl + 1]) * inv_scale;
            }
        __syncthreads();
#pragma unroll
        for (int i = 0; i < 2; ++i) {
            const int p  = tid + i * 512;     // 0..1023
            const int q  = p >> 7;            // local query 0..7
            const int c  = p & 127;           // local channel
            const int m0 = bm + q * 16;       // global row of neighbor k=0
            float vals[KNNV];
            float mx = -3.4e38f;
#pragma unroll
            for (int k = 0; k < KNNV; ++k) {
                vals[k] = sred[(q * 16 + k) * RSTR + c];
                mx = fmaxf(mx, vals[k]);
            }
            float s = 0.f, accv = 0.f;
#pragma unroll
            for (int k = 0; k < KNNV; ++k) {
                float e = __expf(vals[k] - mx);
                int r = g_idx[m0 + k];
                float pv = __half2float(g_pe[(size_t)(m0 + k) * 256 + bn + c])
                         + __half2float(g_v [(size_t)r * 256 + bn + c]);
                s += e;
                accv = fmaf(e, pv, accv);
            }
            const int qg = m0 >> 4;           // global query row
            ((h16*)Cout)[(size_t)qg * 256 + bn + c] = __float2half_rn(accv / s);
        }
        return;
    }

    const bool doRelu = flags & F_RELU;
    const bool oh16   = flags & F_OH16;
    const bool doQK   = flags & F_QK;
#pragma unroll
    for (int mt = 0; mt < 2; ++mt) {
#pragma unroll
        for (int nt = 0; nt < 4; ++nt) {
            int row0 = bm + wm * 32 + mt * 16 + g;
            int col0 = bn + wn * 32 + nt * 8 + 2 * tg;
            float2 lo = __half22float2(*(const __half2*)&acc[mt][nt][0]);
            float2 hi = __half22float2(*(const __half2*)&acc[mt][nt][1]);
#pragma unroll
            for (int h = 0; h < 2; ++h) {
                int row = row0 + h * 8;
                float c0 = h ? hi.x : lo.x;
                float c1 = h ? hi.y : lo.y;
                if (bias) { c0 += bias[col0]; c1 += bias[col0 + 1]; }
                if (doQK) {
                    int n = row >> 4;
                    int r = g_idx[row];
                    float2 qv = *(const float2*)(qa + (size_t)n * 256 + col0);
                    float2 kv = *(const float2*)(ka + (size_t)r * 256 + col0);
                    c0 += qv.x - kv.x;
                    c1 += qv.y - kv.y;
                }
                if (doRelu) { c0 = fmaxf(c0, 0.f); c1 = fmaxf(c1, 0.f); }
                if (oh16) {
                    *(__half2*)((h16*)Cout + (size_t)row * 256 + col0) =
                        __floats2half2_rn(c0, c1);
                } else {
                    if (resid) {
                        c0 += resid[(size_t)row * 256 + col0];
                        c1 += resid[(size_t)row * 256 + col0 + 1];
                    }
                    *(float2*)((float*)Cout + (size_t)row * 256 + col0) =
                        make_float2(c0, c1);
                }
            }
        }
    }
}

// -------------------- prep: convert / transpose / fold --------------------
struct WSrcs { const float* p[4]; };   // wv, pw2, aw2, fw

__global__ __launch_bounds__(256)
void conv_weights_kernel(WSrcs ws)
{
    const int sel = blockIdx.x >> 8;
    const int n   = blockIdx.x & 255;
    const int k   = threadIdx.x;
    g_wt[(size_t)sel * 65536 + n * 256 + k] =
        __float2half_rn(ws.p[sel][k * 256 + n]);
}

// Wqa = wq@aw1, Wka = wk@aw1, Wpa = pw2@aw1 (stored transposed, fp16),
// bpa = pb2@aw1 + ab1 (fp32)
__global__ __launch_bounds__(256)
void fold_kernel(const float* __restrict__ wq, const float* __restrict__ wk,
                 const float* __restrict__ pw2, const float* __restrict__ aw1,
                 const float* __restrict__ pb2, const float* __restrict__ ab1)
{
    const int b = blockIdx.x;
    const int j = threadIdx.x;
    if (b < 768) {
        const int sel = b >> 8;
        const int i   = b & 255;
        const float* src = (sel == 0) ? wq : (sel == 1) ? wk : pw2;
        float s = 0.f;
        for (int d = 0; d < 256; ++d)
            s = fmaf(src[i * 256 + d], aw1[d * 256 + j], s);
        g_wt[(size_t)(WT_WQA + sel) * 65536 + j * 256 + i] = __float2half_rn(s);
    } else {
        float s = ab1[j];
        for (int d = 0; d < 256; ++d)
            s = fmaf(pb2[d], aw1[d * 256 + j], s);
        g_bpa[j] = s;
    }
}

__global__ __launch_bounds__(256)
void conv_x_kernel(const float* __restrict__ x)
{
    const int i4 = blockIdx.x * 256 + threadIdx.x;
    if (i4 < BNP * DIMV / 4) {
        float4 v = *(const float4*)(x + (size_t)i4 * 4);
        __half2* o = (__half2*)(g_xb + (size_t)i4 * 4);
        o[0] = __floats2half2_rn(v.x, v.y);
        o[1] = __floats2half2_rn(v.z, v.w);
    }
}

// -------------------- KNN: warp-collective threshold top-16 --------------------
__device__ __forceinline__ bool dless(float d1, int i1, float d2, int i2) {
    return (d1 < d2) || (d1 == d2 && i1 < i2);
}

#define KNN_SMEM_BYTES (4 * NN * 4)

__global__ __launch_bounds__(256)
void knn_kernel(const float* __restrict__ pos)
{
    extern __shared__ float sm[];
    float* px = sm;
    float* py = sm + NN;
    float* pz = sm + 2 * NN;
    float* sj = sm + 3 * NN;

    const int b = blockIdx.x >> 9;
    const float* pb = pos + (size_t)b * NN * 3;
    for (int j = threadIdx.x; j < NN; j += 256) {
        float x = pb[3 * j], y = pb[3 * j + 1], z = pb[3 * j + 2];
        px[j] = x; py[j] = y; pz[j] = z;
        sj[j] = x * x + y * y + z * z;
    }
    __syncthreads();

    const int warp = threadIdx.x >> 5, lane = threadIdx.x & 31;
    const int q  = blockIdx.x * 8 + warp;
    const int ql = q & (NN - 1);
    const float qx = px[ql], qy = py[ql], qz = pz[ql];
    const float qsq = sj[ql];

    const unsigned FULL = 0xffffffffu;
    float ld  = 3.4e38f; int li   = 0x7fffffff;
    float tau = 3.4e38f; int taui = 0x7fffffff;

#define KNN_INSERT(cd, cj)                                             \
    {                                                                  \
        bool keep = dless(ld, li, (cd), (cj));                         \
        unsigned bal = __ballot_sync(FULL, keep) & 0xffffu;            \
        int p = __popc(bal);                                           \
        float pd = __shfl_up_sync(FULL, ld, 1);                        \
        int   pi = __shfl_up_sync(FULL, li, 1);                        \
        if (lane == p) { ld = (cd); li = (cj); }                       \
        else if (lane > p && lane < 16) { ld = pd; li = pi; }          \
        tau  = __shfl_sync(FULL, ld, 15);                              \
        taui = __shfl_sync(FULL, li, 15);                              \
    }

#define KNN_HANDLE(dd, jj)                                             \
    {                                                                  \
        unsigned any = __ballot_sync(FULL, dless(dd, jj, tau, taui));  \
        while (any) {                                                  \
            int src = __ffs(any) - 1; any &= any - 1;                  \
            float cd = __shfl_sync(FULL, dd, src);                     \
            int   cj = __shfl_sync(FULL, jj, src);                     \
            if (dless(cd, cj, tau, taui)) KNN_INSERT(cd, cj);          \
        }                                                              \
    }

    for (int base = 0; base < NN; base += 128) {
        const int j0 = base + lane;
        const int j1 = j0 + 32;
        const int j2 = j0 + 64;
        const int j3 = j0 + 96;
        float d0 = qsq + sj[j0] - 2.f * (qx * px[j0] + qy * py[j0] + qz * pz[j0]);
        float d1 = qsq + sj[j1] - 2.f * (qx * px[j1] + qy * py[j1] + qz * pz[j1]);
        float d2 = qsq + sj[j2] - 2.f * (qx * px[j2] + qy * py[j2] + qz * pz[j2]);
        float d3 = qsq + sj[j3] - 2.f * (qx * px[j3] + qy * py[j3] + qz * pz[j3]);
        KNN_HANDLE(d0, j0)
        KNN_HANDLE(d1, j1)
        KNN_HANDLE(d2, j2)
        KNN_HANDLE(d3, j3)
    }

    if (lane < KNNV) g_idx[q * KNNV + lane] = b * NN + li;
#undef KNN_INSERT
#undef KNN_HANDLE
}

// ---------- h = relu(rel @ pw1 + pb1) ----------
__global__ __launch_bounds__(256)
void build_h_kernel(const float* __restrict__ pos, const float* __restrict__ pw1,
                    const float* __restrict__ pb1)
{
    const int m = blockIdx.x * 2 + (threadIdx.x >> 7);
    const int d = (threadIdx.x & 127) * 2;
    const int n = m >> 4;
    const int r = g_idx[m];
    const float rx = pos[3 * n]     - pos[3 * r];
    const float ry = pos[3 * n + 1] - pos[3 * r + 1];
    const float rz = pos[3 * n + 2] - pos[3 * r + 2];
    float v0 = pb1[d]   + rx * pw1[d]     + ry * pw1[DIMV + d]     + rz * pw1[2 * DIMV + d];
    float v1 = pb1[d+1] + rx * pw1[d + 1] + ry * pw1[DIMV + d + 1] + rz * pw1[2 * DIMV + d + 1];
    *(__half2*)(g_h + (size_t)m * DIMV + d) =
        __floats2half2_rn(fmaxf(v0, 0.f), fmaxf(v1, 0.f));
}

// -------------------- launch --------------------
extern "C" void kernel_launch(void* const* d_in, const int* in_sizes, int n_in,
                              void* d_out, int out_size)
{
    const float* x   = (const float*)d_in[0];
    const float* pos = (const float*)d_in[1];
    const float* wq  = (const float*)d_in[2];
    const float* wk  = (const float*)d_in[3];
    const float* wv  = (const float*)d_in[4];
    const float* pw1 = (const float*)d_in[5];
    const float* pb1 = (const float*)d_in[6];
    const float* pw2 = (const float*)d_in[7];
    const float* pb2 = (const float*)d_in[8];
    const float* aw1 = (const float*)d_in[9];
    const float* ab1 = (const float*)d_in[10];
    const float* aw2 = (const float*)d_in[11];
    const float* ab2 = (const float*)d_in[12];
    const float* fw  = (const float*)d_in[13];
    const float* fb  = (const float*)d_in[14];
    (void)in_sizes; (void)n_in; (void)out_size;

    float *qa, *ka, *bpa;
    h16 *v, *agg, *h, *pe, *h2, *wt, *xb;
    cudaGetSymbolAddress((void**)&qa,  g_qa);
    cudaGetSymbolAddress((void**)&ka,  g_ka);
    cudaGetSymbolAddress((void**)&v,   g_v);
    cudaGetSymbolAddress((void**)&agg, g_agg);
    cudaGetSymbolAddress((void**)&h,   g_h);
    cudaGetSymbolAddress((void**)&pe,  g_pe);
    cudaGetSymbolAddress((void**)&h2,  g_h2);
    cudaGetSymbolAddress((void**)&wt,  g_wt);
    cudaGetSymbolAddress((void**)&xb,  g_xb);
    cudaGetSymbolAddress((void**)&bpa, g_bpa);

    cudaFuncSetAttribute(gemm_f16_kernel,
                         cudaFuncAttributeMaxDynamicSharedMemorySize, GEMM_SMEM_BYTES);
    cudaFuncSetAttribute(knn_kernel,
                         cudaFuncAttributeMaxDynamicSharedMemorySize, KNN_SMEM_BYTES);

    const h16* wvt  = wt + (size_t)WT_WV  * 65536;
    const h16* pw2t = wt + (size_t)WT_PW2 * 65536;
    const h16* aw2t = wt + (size_t)WT_AW2 * 65536;
    const h16* fwt  = wt + (size_t)WT_FW  * 65536;
    const h16* wqat = wt + (size_t)WT_WQA * 65536;
    const h16* wkat = wt + (size_t)WT_WKA * 65536;
    const h16* wpat = wt + (size_t)WT_WPA * 65536;

    dim3 blk(256);
    dim3 gblk(512);

    // prep
    WSrcs ws; ws.p[0] = wv; ws.p[1] = pw2; ws.p[2] = aw2; ws.p[3] = fw;
    conv_weights_kernel<<<1024, blk>>>(ws);
    fold_kernel<<<769, blk>>>(wq, wk, pw2, aw1, pb2, ab1);
    conv_x_kernel<<<BNP * DIMV / 4 / 256, blk>>>(x);

    // qa, ka, v (triple: fp32, fp32, fp16 outs)
    gemm_f16_kernel<<<dim3(6, BNP / 128), gblk, GEMM_SMEM_BYTES>>>(
        xb, wqat, wkat, wvt, nullptr, nullptr, nullptr,
        nullptr, nullptr, nullptr,
        qa, ka, v, 0, 0, F_OH16);

    // knn
    knn_kernel<<<BNP / 8, blk, KNN_SMEM_BYTES>>>(pos);

    // h = relu(rel@pw1+pb1)
    build_h_kernel<<<M2 / 2, blk>>>(pos, pw1, pb1);

    // pe = h@pw2 + pb2  AND  h2 = relu(h@Wpa + bpa + qa[n] - ka[r])  (dual)
    gemm_f16_kernel<<<dim3(4, M2 / 128), gblk, GEMM_SMEM_BYTES>>>(
        h, pw2t, wpat, nullptr, pb2, bpa, nullptr,
        qa, ka, nullptr,
        pe, h2, nullptr, F_OH16, F_OH16 | F_RELU | F_QK, 0);

    // agg = softmax_K((h2@aw2 + ab2)/16) . (v[idx] + pe)  — fused, smem-staged
    gemm_f16_kernel<<<dim3(2, M2 / 128), gblk, GEMM_SMEM_BYTES>>>(
        h2, aw2t, nullptr, nullptr, ab2, nullptr, nullptr,
        nullptr, nullptr, nullptr,
        agg, nullptr, nullptr, F_SOFTAGG, 0, 0);

    // out = agg@fw + fb + x
    gemm_f16_kernel<<<dim3(2, BNP / 128), gblk, GEMM_SMEM_BYTES>>>(
        agg, fwt, nullptr, nullptr, fb, nullptr, nullptr,
        nullptr, nullptr, x,
        (float*)d_out, nullptr, nullptr, 0, 0, 0);
}

// round 16
// speedup vs baseline: 1.1680x; 1.0273x over previous
#include <cuda_runtime.h>
#include <cuda_fp16.h>
#include <math.h>
#include <stdint.h>

// Problem constants
#define BB   2
#define NN   4096
#define BNP  (BB*NN)        // 8192 rows
#define DIMV 256
#define KNNV 16
#define M2   (BNP*KNNV)     // 131072 rows

typedef __half h16;

// -------------------- scratch --------------------
__device__ float g_qa [BNP*DIMV];
__device__ float g_ka [BNP*DIMV];
__device__ h16   g_v  [BNP*DIMV];
__device__ h16   g_agg[BNP*DIMV];
__device__ int   g_idx[M2];
__device__ h16   g_h  [(size_t)M2*DIMV];
__device__ h16   g_h2 [(size_t)M2*DIMV];
__device__ h16   g_wt [7*DIMV*DIMV];       // transposed fp16 weights [n][k]
__device__ h16   g_xb [BNP*DIMV];
__device__ float g_bpa[DIMV];

#define WT_WV  0
#define WT_PW2 1
#define WT_AW2 2
#define WT_FW  3
#define WT_WQA 4
#define WT_WKA 5
#define WT_WPA 6

// epilogue flags
#define F_RELU    1
#define F_OH16    2
#define F_QK      4

// ==================== fp16 mma.sync GEMM (f16 acc), 512 threads ====
// CTA tile 128x128, BK=64 double-buffered. 16 warps (4x4), 32x32 per warp.
#define BKV   64
#define ASTR  72
#define TBUF  (128*ASTR)
#define GEMM_SMEM_BYTES (4*TBUF*2)  // 73728 B

__device__ __forceinline__ void cp16h(h16* s, const h16* g) {
    uint32_t sa = (uint32_t)__cvta_generic_to_shared(s);
    asm volatile("cp.async.cg.shared.global [%0], [%1], 16;\n" :: "r"(sa), "l"(g));
}
__device__ __forceinline__ void cp16ha(uint32_t sa, const h16* g) {
    asm volatile("cp.async.cg.shared.global [%0], [%1], 16;\n" :: "r"(sa), "l"(g));
}

#define LDSM4(r0, r1, r2, r3, addr)                                          \
    asm volatile("ldmatrix.sync.aligned.m8n8.x4.shared.b16 {%0,%1,%2,%3}, [%4];" \
                 : "=r"(r0), "=r"(r1), "=r"(r2), "=r"(r3) : "r"(addr))

#define MMA_F16(c0, c1, a0, a1, a2, a3, b0, b1)                              \
    asm volatile("mma.sync.aligned.m16n8k16.row.col.f16.f16.f16.f16 "        \
                 "{%0,%1}, {%2,%3,%4,%5}, {%6,%7}, {%0,%1};\n"               \
                 : "+r"(c0), "+r"(c1)                                        \
                 : "r"(a0), "r"(a1), "r"(a2), "r"(a3), "r"(b0), "r"(b1))

__global__ __launch_bounds__(512, 2)
void gemm_f16_kernel(const h16* __restrict__ A,
                     const h16* __restrict__ Bt0, const h16* __restrict__ Bt1,
                     const h16* __restrict__ Bt2,
                     const float* __restrict__ bias0, const float* __restrict__ bias1,
                     const float* __restrict__ bias2,
                     const float* __restrict__ qa, const float* __restrict__ ka,
                     const float* __restrict__ resid,
                     void* __restrict__ out0, void* __restrict__ out1,
                     void* __restrict__ out2,
                     int flags0, int flags1, int flags2)
{
    extern __shared__ h16 smem[];
    h16* As = smem;              // [2][128][ASTR]
    h16* Bs = smem + 2 * TBUF;   // [2][128][ASTR]

    const int tid  = threadIdx.x;
    const int lane = tid & 31;
    const int warp = tid >> 5;        // 0..15
    const int wm   = warp >> 2;       // 0..3
    const int wn   = warp & 3;        // 0..3
    const int bm   = blockIdx.y * 128;

    int sub, bn;
    if (Bt1) { sub = blockIdx.x >> 1; bn = (blockIdx.x & 1) * 128; }
    else     { sub = 0;               bn = blockIdx.x * 128; }
    const h16*   Bt    = (sub == 2) ? Bt2    : (sub == 1) ? Bt1    : Bt0;
    const float* bias  = (sub == 2) ? bias2  : (sub == 1) ? bias1  : bias0;
    void*        Cout  = (sub == 2) ? out2   : (sub == 1) ? out1   : out0;
    const int    flags = (sub == 2) ? flags2 : (sub == 1) ? flags1 : flags0;

    const int g  = lane >> 2;
    const int tg = lane & 3;

    uint32_t acc[2][4][2];
#pragma unroll
    for (int i = 0; i < 2; ++i)
#pragma unroll
        for (int j = 0; j < 4; ++j) { acc[i][j][0] = 0u; acc[i][j][1] = 0u; }

    auto load_tile = [&](int buf, int k0) {
#pragma unroll
        for (int u = 0; u < 2; ++u) {
            int idx = tid + u * 512;
            int row = idx >> 3;
            int c8  = idx & 7;
            cp16h(&As[buf * TBUF + row * ASTR + c8 * 8],
                  A + (size_t)(bm + row) * 256 + k0 + c8 * 8);
        }
#pragma unroll
        for (int u = 0; u < 2; ++u) {
            int idx = tid + u * 512;
            int row = idx >> 3;
            int c8  = idx & 7;
            cp16h(&Bs[buf * TBUF + row * ASTR + c8 * 8],
                  Bt + (size_t)(bn + row) * 256 + k0 + c8 * 8);
        }
        asm volatile("cp.async.commit_group;\n");
    };

    load_tile(0, 0);

    const int sel  = lane >> 3;
    const int rsub = lane & 7;
    const uint32_t sA = (uint32_t)__cvta_generic_to_shared(As);
    const uint32_t sB = (uint32_t)__cvta_generic_to_shared(Bs);
    const uint32_t aBase =
        sA + (uint32_t)(((wm * 32 + rsub + (sel & 1) * 8) * ASTR + (sel >> 1) * 8) * 2);
    const uint32_t bBase =
        sB + (uint32_t)(((wn * 32 + rsub + (sel & 1) * 8) * ASTR + (sel >> 1) * 8) * 2);

    for (int t = 0; t < 4; ++t) {
        const int buf = t & 1;
        if (t < 3) {
            load_tile(buf ^ 1, (t + 1) * BKV);
            asm volatile("cp.async.wait_group 1;\n" ::: "memory");
        } else {
            asm volatile("cp.async.wait_group 0;\n" ::: "memory");
        }
        __syncthreads();

        const uint32_t aT = aBase + (uint32_t)buf * (TBUF * 2);
        const uint32_t bT = bBase + (uint32_t)buf * (TBUF * 2);

#pragma unroll
        for (int ks = 0; ks < 4; ++ks) {
            const uint32_t koff = ks * 16 * 2;
            uint32_t af[2][4], bfr[4][2];
#pragma unroll
            for (int mt = 0; mt < 2; ++mt) {
                LDSM4(af[mt][0], af[mt][1], af[mt][2], af[mt][3],
                      aT + (uint32_t)(mt * 16 * ASTR * 2) + koff);
            }
#pragma unroll
            for (int p = 0; p < 2; ++p) {
                LDSM4(bfr[2 * p][0], bfr[2 * p + 1][0], bfr[2 * p][1], bfr[2 * p + 1][1],
                      bT + (uint32_t)(p * 16 * ASTR * 2) + koff);
            }
#pragma unroll
            for (int mt = 0; mt < 2; ++mt)
#pragma unroll
                for (int nt = 0; nt < 4; ++nt) {
                    MMA_F16(acc[mt][nt][0], acc[mt][nt][1],
                            af[mt][0], af[mt][1], af[mt][2], af[mt][3],
                            bfr[nt][0], bfr[nt][1]);
                }
        }
        __syncthreads();
    }

    const bool doRelu = flags & F_RELU;
    const bool oh16   = flags & F_OH16;
    const bool doQK   = flags & F_QK;
#pragma unroll
    for (int mt = 0; mt < 2; ++mt) {
#pragma unroll
        for (int nt = 0; nt < 4; ++nt) {
            int row0 = bm + wm * 32 + mt * 16 + g;
            int col0 = bn + wn * 32 + nt * 8 + 2 * tg;
            float2 lo = __half22float2(*(const __half2*)&acc[mt][nt][0]);
            float2 hi = __half22float2(*(const __half2*)&acc[mt][nt][1]);
#pragma unroll
            for (int h = 0; h < 2; ++h) {
                int row = row0 + h * 8;
                float c0 = h ? hi.x : lo.x;
                float c1 = h ? hi.y : lo.y;
                if (bias) { c0 += bias[col0]; c1 += bias[col0 + 1]; }
                if (doQK) {
                    int n = row >> 4;
                    int r = g_idx[row];
                    float2 qv = *(const float2*)(qa + (size_t)n * 256 + col0);
                    float2 kv = *(const float2*)(ka + (size_t)r * 256 + col0);
                    c0 += qv.x - kv.x;
                    c1 += qv.y - kv.y;
                }
                if (doRelu) { c0 = fmaxf(c0, 0.f); c1 = fmaxf(c1, 0.f); }
                if (oh16) {
                    *(__half2*)((h16*)Cout + (size_t)row * 256 + col0) =
                        __floats2half2_rn(c0, c1);
                } else {
                    if (resid) {
                        c0 += resid[(size_t)row * 256 + col0];
                        c1 += resid[(size_t)row * 256 + col0 + 1];
                    }
                    *(float2*)((float*)Cout + (size_t)row * 256 + col0) =
                        make_float2(c0, c1);
                }
            }
        }
    }
}

// ==================== fused softagg: a2 = h2@aw2, pe = h@pw2, softmax+agg ====
// BK=32, 4 sources (h2, h, aw2, pw2) double-buffered. 16 warps, 32x32 per warp
// per accumulator set. Stages a2 and pe as fp16 in smem, then per-(query,
// channel) serial softmax over K=16 + aggregate with v gather.
#define SBK   32
#define SSTR  40                     // elems per row (80B, LDSM conflict-free)
#define STILE (128*SSTR)             // 5120 elems
#define SOFT_SMEM_BYTES (8*STILE*2)  // 81920 B
#define PSTR  136                    // staging stride (fp16 elems)

__global__ __launch_bounds__(512, 2)
void softagg_kernel(const float* __restrict__ ab2, const float* __restrict__ pb2)
{
    extern __shared__ h16 smem[];
    const int tid  = threadIdx.x;
    const int lane = tid & 31;
    const int warp = tid >> 5;
    const int wm   = warp >> 2;
    const int wn   = warp & 3;
    const int bm   = blockIdx.y * 128;
    const int bn   = blockIdx.x * 128;

    const h16* aw2t = g_wt + (size_t)WT_AW2 * 65536;
    const h16* pw2t = g_wt + (size_t)WT_PW2 * 65536;

    const int g  = lane >> 2;
    const int tg = lane & 3;

    uint32_t acc_a2[2][4][2], acc_pe[2][4][2];
#pragma unroll
    for (int i = 0; i < 2; ++i)
#pragma unroll
        for (int j = 0; j < 4; ++j) {
            acc_a2[i][j][0] = acc_a2[i][j][1] = 0u;
            acc_pe[i][j][0] = acc_pe[i][j][1] = 0u;
        }

    const int lrow = tid >> 2;        // 0..127
    const int lc4  = tid & 3;         // 16B chunk (4 per 32-elem row)
    auto load_chunk = [&](int buf, int k0) {
        h16* base = smem + (size_t)buf * 4 * STILE + lrow * SSTR + lc4 * 8;
        const size_t goffA = (size_t)(bm + lrow) * 256 + k0 + lc4 * 8;
        const size_t goffB = (size_t)(bn + lrow) * 256 + k0 + lc4 * 8;
        cp16h(base,             g_h2 + goffA);
        cp16h(base + STILE,     g_h  + goffA);
        cp16h(base + 2 * STILE, aw2t + goffB);
        cp16h(base + 3 * STILE, pw2t + goffB);
        asm volatile("cp.async.commit_group;\n");
    };

    load_chunk(0, 0);

    const int sel  = lane >> 3;
    const int rsub = lane & 7;
    const uint32_t sBase = (uint32_t)__cvta_generic_to_shared(smem);
    const uint32_t aOff =
        (uint32_t)(((wm * 32 + rsub + (sel & 1) * 8) * SSTR + (sel >> 1) * 8) * 2);
    const uint32_t bOff =
        (uint32_t)(((wn * 32 + rsub + (sel & 1) * 8) * SSTR + (sel >> 1) * 8) * 2);

    for (int t = 0; t < 8; ++t) {
        const int buf = t & 1;
        if (t < 7) {
            load_chunk(buf ^ 1, (t + 1) * SBK);
            asm volatile("cp.async.wait_group 1;\n" ::: "memory");
        } else {
            asm volatile("cp.async.wait_group 0;\n" ::: "memory");
        }
        __syncthreads();

        const uint32_t tb = sBase + (uint32_t)buf * (4 * STILE * 2);

#pragma unroll
        for (int ks = 0; ks < 2; ++ks) {
            const uint32_t koff = ks * 16 * 2;
            // ---- a2 += h2 @ aw2 ----
            {
                uint32_t af[2][4], bfr[4][2];
#pragma unroll
                for (int mt = 0; mt < 2; ++mt)
                    LDSM4(af[mt][0], af[mt][1], af[mt][2], af[mt][3],
                          tb + aOff + (uint32_t)(mt * 16 * SSTR * 2) + koff);
#pragma unroll
                for (int p = 0; p < 2; ++p)
                    LDSM4(bfr[2*p][0], bfr[2*p+1][0], bfr[2*p][1], bfr[2*p+1][1],
                          tb + (uint32_t)(2 * STILE * 2) + bOff
                             + (uint32_t)(p * 16 * SSTR * 2) + koff);
#pragma unroll
                for (int mt = 0; mt < 2; ++mt)
#pragma unroll
                    for (int nt = 0; nt < 4; ++nt)
                        MMA_F16(acc_a2[mt][nt][0], acc_a2[mt][nt][1],
                                af[mt][0], af[mt][1], af[mt][2], af[mt][3],
                                bfr[nt][0], bfr[nt][1]);
            }
            // ---- pe += h @ pw2 ----
            {
                uint32_t af[2][4], bfr[4][2];
#pragma unroll
                for (int mt = 0; mt < 2; ++mt)
                    LDSM4(af[mt][0], af[mt][1], af[mt][2], af[mt][3],
                          tb + (uint32_t)(STILE * 2) + aOff
                             + (uint32_t)(mt * 16 * SSTR * 2) + koff);
#pragma unroll
                for (int p = 0; p < 2; ++p)
                    LDSM4(bfr[2*p][0], bfr[2*p+1][0], bfr[2*p][1], bfr[2*p+1][1],
                          tb + (uint32_t)(3 * STILE * 2) + bOff
                             + (uint32_t)(p * 16 * SSTR * 2) + koff);
#pragma unroll
                for (int mt = 0; mt < 2; ++mt)
#pragma unroll
                    for (int nt = 0; nt < 4; ++nt)
                        MMA_F16(acc_pe[mt][nt][0], acc_pe[mt][nt][1],
                                af[mt][0], af[mt][1], af[mt][2], af[mt][3],
                                bfr[nt][0], bfr[nt][1]);
            }
        }
        __syncthreads();
    }

    // ---- stage a2 (scaled+bias) and pe (bias) as fp16 ----
    h16* sa2 = smem;                  // [128][PSTR]
    h16* spe = smem + 128 * PSTR;     // [128][PSTR]
    const float inv_scale = 1.0f / 16.0f;
#pragma unroll
    for (int mt = 0; mt < 2; ++mt)
#pragma unroll
        for (int nt = 0; nt < 4; ++nt) {
            int rl = wm * 32 + mt * 16 + g;
            int cl = wn * 32 + nt * 8 + 2 * tg;
            float b0 = ab2[bn + cl], b1 = ab2[bn + cl + 1];
            float p0 = pb2[bn + cl], p1 = pb2[bn + cl + 1];
            float2 lo = __half22float2(*(const __half2*)&acc_a2[mt][nt][0]);
            float2 hi = __half22float2(*(const __half2*)&acc_a2[mt][nt][1]);
            *(__half2*)(sa2 + rl * PSTR + cl) =
                __floats2half2_rn((lo.x + b0) * inv_scale, (lo.y + b1) * inv_scale);
            *(__half2*)(sa2 + (rl + 8) * PSTR + cl) =
                __floats2half2_rn((hi.x + b0) * inv_scale, (hi.y + b1) * inv_scale);
            float2 plo = __half22float2(*(const __half2*)&acc_pe[mt][nt][0]);
            float2 phi = __half22float2(*(const __half2*)&acc_pe[mt][nt][1]);
            *(__half2*)(spe + rl * PSTR + cl) =
                __floats2half2_rn(plo.x + p0, plo.y + p1);
            *(__half2*)(spe + (rl + 8) * PSTR + cl) =
                __floats2half2_rn(phi.x + p0, phi.y + p1);
        }
    __syncthreads();

    // ---- per-(query, channel) softmax over K + aggregate ----
#pragma unroll
    for (int i = 0; i < 2; ++i) {
        const int p  = tid + i * 512;     // 0..1023
        const int q  = p >> 7;            // local query 0..7
        const int c  = p & 127;           // local channel
        const int m0 = bm + q * 16;
        float vals[KNNV];
        float mx = -3.4e38f;
#pragma unroll
        for (int k = 0; k < KNNV; ++k) {
            vals[k] = __half2float(sa2[(q * 16 + k) * PSTR + c]);
            mx = fmaxf(mx, vals[k]);
        }
        float s = 0.f, accv = 0.f;
#pragma unroll
        for (int k = 0; k < KNNV; ++k) {
            float e = __expf(vals[k] - mx);
            int r = g_idx[m0 + k];
            float pv = __half2float(spe[(q * 16 + k) * PSTR + c])
                     + __half2float(g_v[(size_t)r * 256 + bn + c]);
            s += e;
            accv = fmaf(e, pv, accv);
        }
        const int qg = m0 >> 4;
        g_agg[(size_t)qg * 256 + bn + c] = __float2half_rn(accv / s);
    }
}

// -------------------- prep --------------------
struct WSrcs { const float* p[4]; };   // wv, pw2, aw2, fw

__global__ __launch_bounds__(256)
void conv_weights_kernel(WSrcs ws)
{
    const int sel = blockIdx.x >> 8;
    const int n   = blockIdx.x & 255;
    const int k   = threadIdx.x;
    g_wt[(size_t)sel * 65536 + n * 256 + k] =
        __float2half_rn(ws.p[sel][k * 256 + n]);
}

__global__ __launch_bounds__(256)
void fold_kernel(const float* __restrict__ wq, const float* __restrict__ wk,
                 const float* __restrict__ pw2, const float* __restrict__ aw1,
                 const float* __restrict__ pb2, const float* __restrict__ ab1)
{
    const int b = blockIdx.x;
    const int j = threadIdx.x;
    if (b < 768) {
        const int sel = b >> 8;
        const int i   = b & 255;
        const float* src = (sel == 0) ? wq : (sel == 1) ? wk : pw2;
        float s = 0.f;
        for (int d = 0; d < 256; ++d)
            s = fmaf(src[i * 256 + d], aw1[d * 256 + j], s);
        g_wt[(size_t)(WT_WQA + sel) * 65536 + j * 256 + i] = __float2half_rn(s);
    } else {
        float s = ab1[j];
        for (int d = 0; d < 256; ++d)
            s = fmaf(pb2[d], aw1[d * 256 + j], s);
        g_bpa[j] = s;
    }
}

__global__ __launch_bounds__(256)
void conv_x_kernel(const float* __restrict__ x)
{
    const int i4 = blockIdx.x * 256 + threadIdx.x;
    if (i4 < BNP * DIMV / 4) {
        float4 v = *(const float4*)(x + (size_t)i4 * 4);
        __half2* o = (__half2*)(g_xb + (size_t)i4 * 4);
        o[0] = __floats2half2_rn(v.x, v.y);
        o[1] = __floats2half2_rn(v.z, v.w);
    }
}

// -------------------- KNN --------------------
__device__ __forceinline__ bool dless(float d1, int i1, float d2, int i2) {
    return (d1 < d2) || (d1 == d2 && i1 < i2);
}

#define KNN_SMEM_BYTES (4 * NN * 4)

__global__ __launch_bounds__(256)
void knn_kernel(const float* __restrict__ pos)
{
    extern __shared__ float sm[];
    float* px = sm;
    float* py = sm + NN;
    float* pz = sm + 2 * NN;
    float* sj = sm + 3 * NN;

    const int b = blockIdx.x >> 9;
    const float* pb = pos + (size_t)b * NN * 3;
    for (int j = threadIdx.x; j < NN; j += 256) {
        float x = pb[3 * j], y = pb[3 * j + 1], z = pb[3 * j + 2];
        px[j] = x; py[j] = y; pz[j] = z;
        sj[j] = x * x + y * y + z * z;
    }
    __syncthreads();

    const int warp = threadIdx.x >> 5, lane = threadIdx.x & 31;
    const int q  = blockIdx.x * 8 + warp;
    const int ql = q & (NN - 1);
    const float qx = px[ql], qy = py[ql], qz = pz[ql];
    const float qsq = sj[ql];

    const unsigned FULL = 0xffffffffu;
    float ld  = 3.4e38f; int li   = 0x7fffffff;
    float tau = 3.4e38f; int taui = 0x7fffffff;

#define KNN_INSERT(cd, cj)                                             \
    {                                                                  \
        bool keep = dless(ld, li, (cd), (cj));                         \
        unsigned bal = __ballot_sync(FULL, keep) & 0xffffu;            \
        int p = __popc(bal);                                           \
        float pd = __shfl_up_sync(FULL, ld, 1);                        \
        int   pi = __shfl_up_sync(FULL, li, 1);                        \
        if (lane == p) { ld = (cd); li = (cj); }                       \
        else if (lane > p && lane < 16) { ld = pd; li = pi; }          \
        tau  = __shfl_sync(FULL, ld, 15);                              \
        taui = __shfl_sync(FULL, li, 15);                              \
    }

#define KNN_HANDLE(dd, jj)                                             \
    {                                                                  \
        unsigned any = __ballot_sync(FULL, dless(dd, jj, tau, taui));  \
        while (any) {                                                  \
            int src = __ffs(any) - 1; any &= any - 1;                  \
            float cd = __shfl_sync(FULL, dd, src);                     \
            int   cj = __shfl_sync(FULL, jj, src);                     \
            if (dless(cd, cj, tau, taui)) KNN_INSERT(cd, cj);          \
        }                                                              \
    }

    for (int base = 0; base < NN; base += 128) {
        const int j0 = base + lane;
        const int j1 = j0 + 32;
        const int j2 = j0 + 64;
        const int j3 = j0 + 96;
        float d0 = qsq + sj[j0] - 2.f * (qx * px[j0] + qy * py[j0] + qz * pz[j0]);
        float d1 = qsq + sj[j1] - 2.f * (qx * px[j1] + qy * py[j1] + qz * pz[j1]);
        float d2 = qsq + sj[j2] - 2.f * (qx * px[j2] + qy * py[j2] + qz * pz[j2]);
        float d3 = qsq + sj[j3] - 2.f * (qx * px[j3] + qy * py[j3] + qz * pz[j3]);
        KNN_HANDLE(d0, j0)
        KNN_HANDLE(d1, j1)
        KNN_HANDLE(d2, j2)
        KNN_HANDLE(d3, j3)
    }

    if (lane < KNNV) g_idx[q * KNNV + lane] = b * NN + li;
#undef KNN_INSERT
#undef KNN_HANDLE
}

// ---------- h = relu(rel @ pw1 + pb1) ----------
__global__ __launch_bounds__(256)
void build_h_kernel(const float* __restrict__ pos, const float* __restrict__ pw1,
                    const float* __restrict__ pb1)
{
    const int m = blockIdx.x * 2 + (threadIdx.x >> 7);
    const int d = (threadIdx.x & 127) * 2;
    const int n = m >> 4;
    const int r = g_idx[m];
    const float rx = pos[3 * n]     - pos[3 * r];
    const float ry = pos[3 * n + 1] - pos[3 * r + 1];
    const float rz = pos[3 * n + 2] - pos[3 * r + 2];
    float v0 = pb1[d]   + rx * pw1[d]     + ry * pw1[DIMV + d]     + rz * pw1[2 * DIMV + d];
    float v1 = pb1[d+1] + rx * pw1[d + 1] + ry * pw1[DIMV + d + 1] + rz * pw1[2 * DIMV + d + 1];
    *(__half2*)(g_h + (size_t)m * DIMV + d) =
        __floats2half2_rn(fmaxf(v0, 0.f), fmaxf(v1, 0.f));
}

// -------------------- launch --------------------
extern "C" void kernel_launch(void* const* d_in, const int* in_sizes, int n_in,
                              void* d_out, int out_size)
{
    const float* x   = (const float*)d_in[0];
    const float* pos = (const float*)d_in[1];
    const float* wq  = (const float*)d_in[2];
    const float* wk  = (const float*)d_in[3];
    const float* wv  = (const float*)d_in[4];
    const float* pw1 = (const float*)d_in[5];
    const float* pb1 = (const float*)d_in[6];
    const float* pw2 = (const float*)d_in[7];
    const float* pb2 = (const float*)d_in[8];
    const float* aw1 = (const float*)d_in[9];
    const float* ab1 = (const float*)d_in[10];
    const float* aw2 = (const float*)d_in[11];
    const float* ab2 = (const float*)d_in[12];
    const float* fw  = (const float*)d_in[13];
    const float* fb  = (const float*)d_in[14];
    (void)in_sizes; (void)n_in; (void)out_size;

    float *qa, *ka, *bpa;
    h16 *v, *agg, *h, *h2, *wt, *xb;
    cudaGetSymbolAddress((void**)&qa,  g_qa);
    cudaGetSymbolAddress((void**)&ka,  g_ka);
    cudaGetSymbolAddress((void**)&v,   g_v);
    cudaGetSymbolAddress((void**)&agg, g_agg);
    cudaGetSymbolAddress((void**)&h,   g_h);
    cudaGetSymbolAddress((void**)&h2,  g_h2);
    cudaGetSymbolAddress((void**)&wt,  g_wt);
    cudaGetSymbolAddress((void**)&xb,  g_xb);
    cudaGetSymbolAddress((void**)&bpa, g_bpa);

    cudaFuncSetAttribute(gemm_f16_kernel,
                         cudaFuncAttributeMaxDynamicSharedMemorySize, GEMM_SMEM_BYTES);
    cudaFuncSetAttribute(softagg_kernel,
                         cudaFuncAttributeMaxDynamicSharedMemorySize, SOFT_SMEM_BYTES);
    cudaFuncSetAttribute(knn_kernel,
                         cudaFuncAttributeMaxDynamicSharedMemorySize, KNN_SMEM_BYTES);

    const h16* wvt  = wt + (size_t)WT_WV  * 65536;
    const h16* fwt  = wt + (size_t)WT_FW  * 65536;
    const h16* wqat = wt + (size_t)WT_WQA * 65536;
    const h16* wkat = wt + (size_t)WT_WKA * 65536;
    const h16* wpat = wt + (size_t)WT_WPA * 65536;

    dim3 blk(256);
    dim3 gblk(512);

    // prep
    WSrcs ws; ws.p[0] = wv; ws.p[1] = pw2; ws.p[2] = aw2; ws.p[3] = fw;
    conv_weights_kernel<<<1024, blk>>>(ws);
    fold_kernel<<<769, blk>>>(wq, wk, pw2, aw1, pb2, ab1);
    conv_x_kernel<<<BNP * DIMV / 4 / 256, blk>>>(x);

    // qa, ka, v (triple: fp32, fp32, fp16 outs)
    gemm_f16_kernel<<<dim3(6, BNP / 128), gblk, GEMM_SMEM_BYTES>>>(
        xb, wqat, wkat, wvt, nullptr, nullptr, nullptr,
        nullptr, nullptr, nullptr,
        qa, ka, v, 0, 0, F_OH16);

    // knn
    knn_kernel<<<BNP / 8, blk, KNN_SMEM_BYTES>>>(pos);

    // h = relu(rel@pw1+pb1)
    build_h_kernel<<<M2 / 2, blk>>>(pos, pw1, pb1);

    // h2 = relu(h@Wpa + bpa + qa[n] - ka[r])   (single output)
    gemm_f16_kernel<<<dim3(2, M2 / 128), gblk, GEMM_SMEM_BYTES>>>(
        h, wpat, nullptr, nullptr, bpa, nullptr, nullptr,
        qa, ka, nullptr,
        h2, nullptr, nullptr, F_OH16 | F_RELU | F_QK, 0, 0);

    // fused: a2 = h2@aw2+ab2, pe = h@pw2+pb2, softmax_K + aggregate -> agg
    softagg_kernel<<<dim3(2, M2 / 128), gblk, SOFT_SMEM_BYTES>>>(ab2, pb2);

    // out = agg@fw + fb + x
    gemm_f16_kernel<<<dim3(2, BNP / 128), gblk, GEMM_SMEM_BYTES>>>(
        agg, fwt, nullptr, nullptr, fb, nullptr, nullptr,
        nullptr, nullptr, x,
        (float*)d_out, nullptr, nullptr, 0, 0, 0);
}